// round 3
// baseline (speedup 1.0000x reference)
#include <cuda_runtime.h>
#include <math.h>

#define D      512
#define H      1024
#define SEQ    4096
#define BATCH  4
#define CHUNK  256
#define NCHUNK 16
#define NROWS  (BATCH * CHUNK)   // 1024 rows per chunk step
#define TOTROWS (BATCH * SEQ)    // 16384 rows total

// ---------------- scratch (static device allocations; alloc-free at runtime) ----
__device__ float g_W1[D * H];
__device__ float g_W2[H * D];
__device__ float g_S1[D * H];
__device__ float g_S2[H * D];
__device__ float g_xc[NROWS * D];
__device__ float g_k [NROWS * D];
__device__ float g_v [NROWS * D];
__device__ float g_h [NROWS * H];
__device__ float g_a [NROWS * H];
__device__ float g_e [NROWS * D];
__device__ float g_dh[NROWS * H];
__device__ float g_g1[D * H];
__device__ float g_g2[H * D];
__device__ float g_q [TOTROWS * D];
__device__ float g_af[TOTROWS * H];

// ---------------- math helpers --------------------------------------------------
__device__ __forceinline__ float gelu_exact(float x) {
    return 0.5f * x * (1.0f + erff(x * 0.70710678118654752f));
}
__device__ __forceinline__ float dgelu_exact(float x) {
    // d/dx [0.5 x (1+erf(x/sqrt2))] = 0.5(1+erf(x/sqrt2)) + x * N(x;0,1)
    return 0.5f * (1.0f + erff(x * 0.70710678118654752f))
         + x * 0.39894228040143268f * expf(-0.5f * x * x);
}

// ---------------- epilogue modes -------------------------------------------------
#define EPI_NONE     0   // C = AB
#define EPI_GELU_H   1   // aux2 = AB; C = gelu(AB)
#define EPI_SUBSCALE 2   // C = (AB - aux) * scale
#define EPI_DGELU    3   // C = AB * dgelu(aux)
#define EPI_GELU     4   // C = gelu(AB)

// ---------------- generic tiled GEMM (row-major), 64x64x16 tile, 4x4 per thread --
// Logical: C[M,N] = op(A)[M,K] @ op(B)[K,N].
// TA: A physically stored [K,M] row-major.  TB: B physically stored [N,K] row-major.
// All of M, N, K are multiples of 64/16 in this problem: no bounds checks.
template <bool TA, bool TB, int EPI>
__global__ __launch_bounds__(256)
void gemm_kernel(const float* __restrict__ A, const float* __restrict__ B,
                 float* __restrict__ C, int M, int N, int K,
                 const float* __restrict__ aux, float* __restrict__ aux2,
                 float scale) {
    __shared__ float As[16][64];
    __shared__ float Bs[16][64];

    const int tid = threadIdx.x;
    const int tx = tid & 15;      // 0..15 -> column group
    const int ty = tid >> 4;      // 0..15 -> row group
    const int bm = blockIdx.y * 64;
    const int bn = blockIdx.x * 64;

    float acc[4][4];
#pragma unroll
    for (int i = 0; i < 4; ++i)
#pragma unroll
        for (int j = 0; j < 4; ++j) acc[i][j] = 0.0f;

    for (int k0 = 0; k0 < K; k0 += 16) {
        // ---- load A tile into As[k][m] ----
        if (!TA) {
            int m  = tid >> 2;            // 0..63
            int kq = tid & 3;             // 0..3 (4 k-floats each)
            float4 t = *(const float4*)(A + (size_t)(bm + m) * K + k0 + kq * 4);
            As[kq * 4 + 0][m] = t.x;
            As[kq * 4 + 1][m] = t.y;
            As[kq * 4 + 2][m] = t.z;
            As[kq * 4 + 3][m] = t.w;
        } else {
            int kk = tid >> 4;            // 0..15
            int mq = tid & 15;            // 0..15
            float4 t = *(const float4*)(A + (size_t)(k0 + kk) * M + bm + mq * 4);
            *(float4*)&As[kk][mq * 4] = t;
        }
        // ---- load B tile into Bs[k][n] ----
        if (!TB) {
            int kk = tid >> 4;
            int nq = tid & 15;
            float4 t = *(const float4*)(B + (size_t)(k0 + kk) * N + bn + nq * 4);
            *(float4*)&Bs[kk][nq * 4] = t;
        } else {
            int n  = tid >> 2;
            int kq = tid & 3;
            float4 t = *(const float4*)(B + (size_t)(bn + n) * K + k0 + kq * 4);
            Bs[kq * 4 + 0][n] = t.x;
            Bs[kq * 4 + 1][n] = t.y;
            Bs[kq * 4 + 2][n] = t.z;
            Bs[kq * 4 + 3][n] = t.w;
        }
        __syncthreads();

#pragma unroll
        for (int kk = 0; kk < 16; ++kk) {
            float4 av = *(const float4*)&As[kk][ty * 4];
            float4 bv = *(const float4*)&Bs[kk][tx * 4];
            float a0 = av.x, a1 = av.y, a2 = av.z, a3 = av.w;
            float b0 = bv.x, b1 = bv.y, b2 = bv.z, b3 = bv.w;
            acc[0][0] += a0 * b0; acc[0][1] += a0 * b1; acc[0][2] += a0 * b2; acc[0][3] += a0 * b3;
            acc[1][0] += a1 * b0; acc[1][1] += a1 * b1; acc[1][2] += a1 * b2; acc[1][3] += a1 * b3;
            acc[2][0] += a2 * b0; acc[2][1] += a2 * b1; acc[2][2] += a2 * b2; acc[2][3] += a2 * b3;
            acc[3][0] += a3 * b0; acc[3][1] += a3 * b1; acc[3][2] += a3 * b2; acc[3][3] += a3 * b3;
        }
        __syncthreads();
    }

#pragma unroll
    for (int i = 0; i < 4; ++i) {
#pragma unroll
        for (int j = 0; j < 4; ++j) {
            size_t idx = (size_t)(bm + ty * 4 + i) * N + (bn + tx * 4 + j);
            float v = acc[i][j];
            if (EPI == EPI_NONE) {
                C[idx] = v;
            } else if (EPI == EPI_GELU_H) {
                aux2[idx] = v;
                C[idx] = gelu_exact(v);
            } else if (EPI == EPI_SUBSCALE) {
                C[idx] = (v - aux[idx]) * scale;
            } else if (EPI == EPI_DGELU) {
                C[idx] = v * dgelu_exact(aux[idx]);
            } else if (EPI == EPI_GELU) {
                C[idx] = gelu_exact(v);
            }
        }
    }
}

// ---------------- chunk gather: xc[1024,512] = x[:, t*256:(t+1)*256, :] ----------
__global__ void gather_chunk_kernel(const float* __restrict__ x, float* __restrict__ xc, int t) {
    int i = blockIdx.x * blockDim.x + threadIdx.x;     // float4 index
    int e = i * 4;
    if (e >= NROWS * D) return;
    int m = e / D;
    int d = e - m * D;
    int b = m >> 8;              // m / CHUNK
    int r = m & 255;             // m % CHUNK
    size_t src = ((size_t)(b * SEQ + t * CHUNK + r)) * D + d;
    *(float4*)(xc + e) = *(const float4*)(x + src);
}

// ---------------- momentum + decayed weight update -------------------------------
__global__ void update_kernel(const float* __restrict__ a_t, const float* __restrict__ l_t,
                              const float* __restrict__ dc_t, const int* __restrict__ um) {
    if (*um == 0) return;
    int i = blockIdx.x * blockDim.x + threadIdx.x;
    float alpha = 1.0f / (1.0f + expf(-*a_t));
    float lr    = 1.0f / (1.0f + expf(-*l_t));
    float decay = 1.0f / (1.0f + expf(-*dc_t));
    if (i < D * H) {
        float s = decay * g_S1[i] - lr * g_g1[i];
        g_S1[i] = s;
        g_W1[i] = (1.0f - alpha) * g_W1[i] + s;
    } else {
        i -= D * H;
        if (i < H * D) {
            float s = decay * g_S2[i] - lr * g_g2[i];
            g_S2[i] = s;
            g_W2[i] = (1.0f - alpha) * g_W2[i] + s;
        }
    }
}

// ---------------- launch helpers ------------------------------------------------
static inline dim3 gemm_grid(int M, int N) { return dim3(N / 64, M / 64); }

extern "C" void kernel_launch(void* const* d_in, const int* in_sizes, int n_in,
                              void* d_out, int out_size) {
    const float* x    = (const float*)d_in[0];
    const float* w_q  = (const float*)d_in[1];
    const float* w_k  = (const float*)d_in[2];
    const float* w_v  = (const float*)d_in[3];
    const float* mw1  = (const float*)d_in[4];
    const float* mw2  = (const float*)d_in[5];
    const float* a_t  = (const float*)d_in[6];
    const float* l_t  = (const float*)d_in[7];
    const float* dc_t = (const float*)d_in[8];
    const int*   um   = (const int*)  d_in[9];
    float* out = (float*)d_out;

    float *W1, *W2, *S1, *S2, *xc, *k_, *v_, *h_, *a_, *e_, *dh_, *g1_, *g2_, *q_, *af_;
    cudaGetSymbolAddress((void**)&W1,  g_W1);
    cudaGetSymbolAddress((void**)&W2,  g_W2);
    cudaGetSymbolAddress((void**)&S1,  g_S1);
    cudaGetSymbolAddress((void**)&S2,  g_S2);
    cudaGetSymbolAddress((void**)&xc,  g_xc);
    cudaGetSymbolAddress((void**)&k_,  g_k);
    cudaGetSymbolAddress((void**)&v_,  g_v);
    cudaGetSymbolAddress((void**)&h_,  g_h);
    cudaGetSymbolAddress((void**)&a_,  g_a);
    cudaGetSymbolAddress((void**)&e_,  g_e);
    cudaGetSymbolAddress((void**)&dh_, g_dh);
    cudaGetSymbolAddress((void**)&g1_, g_g1);
    cudaGetSymbolAddress((void**)&g2_, g_g2);
    cudaGetSymbolAddress((void**)&q_,  g_q);
    cudaGetSymbolAddress((void**)&af_, g_af);

    // init memory state
    cudaMemcpyAsync(W1, mw1, sizeof(float) * D * H, cudaMemcpyDeviceToDevice);
    cudaMemcpyAsync(W2, mw2, sizeof(float) * H * D, cudaMemcpyDeviceToDevice);
    cudaMemsetAsync(S1, 0, sizeof(float) * D * H);
    cudaMemsetAsync(S2, 0, sizeof(float) * H * D);

    const float escale = 2.0f / (float)(NROWS * D);

    for (int t = 0; t < NCHUNK; ++t) {
        gather_chunk_kernel<<<(NROWS * D / 4 + 255) / 256, 256>>>(x, xc, t);
        // k = xc @ w_k ; v = xc @ w_v
        gemm_kernel<false, false, EPI_NONE><<<gemm_grid(NROWS, D), 256>>>(
            xc, w_k, k_, NROWS, D, D, nullptr, nullptr, 0.f);
        gemm_kernel<false, false, EPI_NONE><<<gemm_grid(NROWS, D), 256>>>(
            xc, w_v, v_, NROWS, D, D, nullptr, nullptr, 0.f);
        // h = k @ W1 ; a = gelu(h)
        gemm_kernel<false, false, EPI_GELU_H><<<gemm_grid(NROWS, H), 256>>>(
            k_, W1, a_, NROWS, H, D, nullptr, h_, 0.f);
        // e = (a @ W2 - v) * 2/(N*D)
        gemm_kernel<false, false, EPI_SUBSCALE><<<gemm_grid(NROWS, D), 256>>>(
            a_, W2, e_, NROWS, D, H, v_, nullptr, escale);
        // g2 = a^T @ e        [H, D]
        gemm_kernel<true, false, EPI_NONE><<<gemm_grid(H, D), 256>>>(
            a_, e_, g2_, H, D, NROWS, nullptr, nullptr, 0.f);
        // dh = (e @ W2^T) * dgelu(h)    [N, H]
        gemm_kernel<false, true, EPI_DGELU><<<gemm_grid(NROWS, H), 256>>>(
            e_, W2, dh_, NROWS, H, D, h_, nullptr, 0.f);
        // g1 = k^T @ dh       [D, H]
        gemm_kernel<true, false, EPI_NONE><<<gemm_grid(D, H), 256>>>(
            k_, dh_, g1_, D, H, NROWS, nullptr, nullptr, 0.f);
        // S/W updates
        update_kernel<<<(2 * D * H + 255) / 256, 256>>>(a_t, l_t, dc_t, um);
    }

    // read-out: out = gelu((x @ w_q) @ W1) @ W2
    gemm_kernel<false, false, EPI_NONE><<<gemm_grid(TOTROWS, D), 256>>>(
        x, w_q, q_, TOTROWS, D, D, nullptr, nullptr, 0.f);
    gemm_kernel<false, false, EPI_GELU><<<gemm_grid(TOTROWS, H), 256>>>(
        q_, W1, af_, TOTROWS, H, D, nullptr, nullptr, 0.f);
    gemm_kernel<false, false, EPI_NONE><<<gemm_grid(TOTROWS, D), 256>>>(
        af_, W2, out, TOTROWS, D, H, nullptr, nullptr, 0.f);
}

// round 7
// speedup vs baseline: 1.9677x; 1.9677x over previous
#include <cuda_runtime.h>
#include <math.h>
#include <stdint.h>

#define D      512
#define H      1024
#define SEQ    4096
#define BATCH  4
#define CHUNK  256
#define NCHUNK 16
#define NROWS  (BATCH * CHUNK)   // 1024 rows per chunk step
#define TOTROWS (BATCH * SEQ)    // 16384 rows total

// ---------------- scratch (static device allocations; alloc-free at runtime) ----
__device__ float g_W1[D * H];
__device__ float g_W2[H * D];
__device__ float g_S1[D * H];
__device__ float g_S2[H * D];
__device__ float g_k [NROWS * D];
__device__ float g_v [NROWS * D];
__device__ float g_h [NROWS * H];
__device__ float g_a [NROWS * H];
__device__ float g_e [NROWS * D];
__device__ float g_dh[NROWS * H];
__device__ float g_g1[D * H];
__device__ float g_g2[H * D];
__device__ float g_q [TOTROWS * D];
__device__ float g_af[TOTROWS * H];

// ---------------- math helpers --------------------------------------------------
__device__ __forceinline__ float gelu_exact(float x) {
    return 0.5f * x * (1.0f + erff(x * 0.70710678118654752f));
}
__device__ __forceinline__ float dgelu_exact(float x) {
    return 0.5f * (1.0f + erff(x * 0.70710678118654752f))
         + x * 0.39894228040143268f * expf(-0.5f * x * x);
}
__device__ __forceinline__ uint32_t f2tf(float x) {
    uint32_t u;
    asm("cvt.rna.tf32.f32 %0, %1;" : "=r"(u) : "f"(x));
    return u;
}

// ---------------- epilogue modes -------------------------------------------------
#define EPI_NONE     0   // C = AB
#define EPI_GELU_H   1   // aux2 = AB; C = gelu(AB)
#define EPI_SUBSCALE 2   // C = (AB - aux) * scale
#define EPI_DGELU    3   // C = AB * dgelu(aux)
#define EPI_GELU     4   // C = gelu(AB)

// ---------------- tf32 tensor-core GEMM -----------------------------------------
// Logical: C[M,N] = op(A)[M,K] @ op(B)[K,N].
// TA: A physically [K,M] row-major.  TB: B physically [N,K] row-major.
// CHUNKA: A row m maps to global row (m/CHUNK)*SEQ + chunk_t*CHUNK + (m%CHUNK).
// Block tile 64x64x32; 4 warps, each computes 32x32 via m16n8k8 tf32 mma.
// M,N multiples of 64; K multiple of 32 (holds for every shape here).

#define ASTRIDE 36   // 36 % 32 == 4  -> A-frag LDS banks (4g + tg) unique
#define BSTRIDE 72   // 72 % 32 == 8  -> B-frag LDS banks (8tg + g) unique

__device__ __forceinline__ void mma_tf32(float c[4], const uint32_t a[4], const uint32_t b[2]) {
    asm volatile(
        "mma.sync.aligned.m16n8k8.row.col.f32.tf32.tf32.f32 "
        "{%0,%1,%2,%3}, {%4,%5,%6,%7}, {%8,%9}, {%0,%1,%2,%3};"
        : "+f"(c[0]), "+f"(c[1]), "+f"(c[2]), "+f"(c[3])
        : "r"(a[0]), "r"(a[1]), "r"(a[2]), "r"(a[3]), "r"(b[0]), "r"(b[1]));
}

template <bool TA, bool TB, int EPI, bool CHUNKA>
__global__ __launch_bounds__(128)
void gemm_kernel(const float* __restrict__ A, const float* __restrict__ B,
                 float* __restrict__ C, int M, int N, int K,
                 const float* __restrict__ aux, float* __restrict__ aux2,
                 float scale, int chunk_t) {
    __shared__ __align__(16) uint32_t As[64 * ASTRIDE];
    __shared__ __align__(16) uint32_t Bs[32 * BSTRIDE];

    const int tid  = threadIdx.x;
    const int lane = tid & 31;
    const int warp = tid >> 5;
    const int g  = lane >> 2;     // 0..7
    const int tg = lane & 3;      // 0..3
    const int wm = warp >> 1;     // 0..1
    const int wn = warp & 1;      // 0..1
    const int bm = blockIdx.y * 64;
    const int bn = blockIdx.x * 64;

    float c[2][4][4];
#pragma unroll
    for (int mt = 0; mt < 2; ++mt)
#pragma unroll
        for (int nt = 0; nt < 4; ++nt)
#pragma unroll
            for (int r = 0; r < 4; ++r) c[mt][nt][r] = 0.0f;

    for (int k0 = 0; k0 < K; k0 += 32) {
        // ---- A tile -> As[m][k] (64 x 32) ----
        if (!TA) {
#pragma unroll
            for (int i = 0; i < 4; ++i) {
                int idx = tid + i * 128;              // 0..511 float4s
                int row = idx >> 3;                   // 0..63
                int c4  = (idx & 7) * 4;              // 0..28
                int grow = bm + row;
                if (CHUNKA) grow = (grow >> 8) * SEQ + chunk_t * CHUNK + (grow & 255);
                float4 t = *(const float4*)(A + (size_t)grow * K + k0 + c4);
                uint4 u = make_uint4(f2tf(t.x), f2tf(t.y), f2tf(t.z), f2tf(t.w));
                *(uint4*)&As[row * ASTRIDE + c4] = u;
            }
        } else {
#pragma unroll
            for (int i = 0; i < 4; ++i) {
                int idx = tid + i * 128;
                int kk = idx >> 4;                    // 0..31
                int m4 = (idx & 15) * 4;              // 0..60
                float4 t = *(const float4*)(A + (size_t)(k0 + kk) * M + bm + m4);
                As[(m4 + 0) * ASTRIDE + kk] = f2tf(t.x);
                As[(m4 + 1) * ASTRIDE + kk] = f2tf(t.y);
                As[(m4 + 2) * ASTRIDE + kk] = f2tf(t.z);
                As[(m4 + 3) * ASTRIDE + kk] = f2tf(t.w);
            }
        }
        // ---- B tile -> Bs[k][n] (32 x 64) ----
        if (!TB) {
#pragma unroll
            for (int i = 0; i < 4; ++i) {
                int idx = tid + i * 128;
                int kk = idx >> 4;                    // 0..31
                int n4 = (idx & 15) * 4;
                float4 t = *(const float4*)(B + (size_t)(k0 + kk) * N + bn + n4);
                uint4 u = make_uint4(f2tf(t.x), f2tf(t.y), f2tf(t.z), f2tf(t.w));
                *(uint4*)&Bs[kk * BSTRIDE + n4] = u;
            }
        } else {
#pragma unroll
            for (int i = 0; i < 4; ++i) {
                int idx = tid + i * 128;
                int n  = idx >> 3;                    // 0..63
                int c4 = (idx & 7) * 4;               // 0..28
                float4 t = *(const float4*)(B + (size_t)(bn + n) * K + k0 + c4);
                Bs[(c4 + 0) * BSTRIDE + n] = f2tf(t.x);
                Bs[(c4 + 1) * BSTRIDE + n] = f2tf(t.y);
                Bs[(c4 + 2) * BSTRIDE + n] = f2tf(t.z);
                Bs[(c4 + 3) * BSTRIDE + n] = f2tf(t.w);
            }
        }
        __syncthreads();

#pragma unroll
        for (int kk = 0; kk < 32; kk += 8) {
            uint32_t af[2][4];
            uint32_t bf[4][2];
#pragma unroll
            for (int mt = 0; mt < 2; ++mt) {
                int r0 = wm * 32 + mt * 16;
                af[mt][0] = As[(r0 + g)     * ASTRIDE + kk + tg];
                af[mt][1] = As[(r0 + g + 8) * ASTRIDE + kk + tg];
                af[mt][2] = As[(r0 + g)     * ASTRIDE + kk + tg + 4];
                af[mt][3] = As[(r0 + g + 8) * ASTRIDE + kk + tg + 4];
            }
#pragma unroll
            for (int nt = 0; nt < 4; ++nt) {
                int cn = wn * 32 + nt * 8 + g;
                bf[nt][0] = Bs[(kk + tg)     * BSTRIDE + cn];
                bf[nt][1] = Bs[(kk + tg + 4) * BSTRIDE + cn];
            }
#pragma unroll
            for (int mt = 0; mt < 2; ++mt)
#pragma unroll
                for (int nt = 0; nt < 4; ++nt)
                    mma_tf32(c[mt][nt], af[mt], bf[nt]);
        }
        __syncthreads();
    }

    // ---- epilogue: per thread 8 float2 pairs ----
#pragma unroll
    for (int mt = 0; mt < 2; ++mt) {
#pragma unroll
        for (int nt = 0; nt < 4; ++nt) {
#pragma unroll
            for (int half = 0; half < 2; ++half) {
                int row = bm + wm * 32 + mt * 16 + g + half * 8;
                int col = bn + wn * 32 + nt * 8 + 2 * tg;
                size_t idx = (size_t)row * N + col;
                float v0 = c[mt][nt][half * 2 + 0];
                float v1 = c[mt][nt][half * 2 + 1];
                if (EPI == EPI_NONE) {
                    *(float2*)(C + idx) = make_float2(v0, v1);
                } else if (EPI == EPI_GELU_H) {
                    *(float2*)(aux2 + idx) = make_float2(v0, v1);
                    *(float2*)(C + idx) = make_float2(gelu_exact(v0), gelu_exact(v1));
                } else if (EPI == EPI_SUBSCALE) {
                    float2 a2 = *(const float2*)(aux + idx);
                    *(float2*)(C + idx) = make_float2((v0 - a2.x) * scale, (v1 - a2.y) * scale);
                } else if (EPI == EPI_DGELU) {
                    float2 a2 = *(const float2*)(aux + idx);
                    *(float2*)(C + idx) = make_float2(v0 * dgelu_exact(a2.x), v1 * dgelu_exact(a2.y));
                } else if (EPI == EPI_GELU) {
                    *(float2*)(C + idx) = make_float2(gelu_exact(v0), gelu_exact(v1));
                }
            }
        }
    }
}

// ---------------- momentum + decayed weight update -------------------------------
__global__ void update_kernel(const float* __restrict__ a_t, const float* __restrict__ l_t,
                              const float* __restrict__ dc_t, const int* __restrict__ um) {
    if (*um == 0) return;
    int i = blockIdx.x * blockDim.x + threadIdx.x;
    float alpha = 1.0f / (1.0f + expf(-*a_t));
    float lr    = 1.0f / (1.0f + expf(-*l_t));
    float decay = 1.0f / (1.0f + expf(-*dc_t));
    if (i < D * H) {
        float s = decay * g_S1[i] - lr * g_g1[i];
        g_S1[i] = s;
        g_W1[i] = (1.0f - alpha) * g_W1[i] + s;
    } else {
        i -= D * H;
        if (i < H * D) {
            float s = decay * g_S2[i] - lr * g_g2[i];
            g_S2[i] = s;
            g_W2[i] = (1.0f - alpha) * g_W2[i] + s;
        }
    }
}

// ---------------- launch helpers ------------------------------------------------
static inline dim3 gemm_grid(int M, int N) { return dim3(N / 64, M / 64); }

extern "C" void kernel_launch(void* const* d_in, const int* in_sizes, int n_in,
                              void* d_out, int out_size) {
    const float* x    = (const float*)d_in[0];
    const float* w_q  = (const float*)d_in[1];
    const float* w_k  = (const float*)d_in[2];
    const float* w_v  = (const float*)d_in[3];
    const float* mw1  = (const float*)d_in[4];
    const float* mw2  = (const float*)d_in[5];
    const float* a_t  = (const float*)d_in[6];
    const float* l_t  = (const float*)d_in[7];
    const float* dc_t = (const float*)d_in[8];
    const int*   um   = (const int*)  d_in[9];
    float* out = (float*)d_out;

    float *W1, *W2, *S1, *S2, *k_, *v_, *h_, *a_, *e_, *dh_, *g1_, *g2_, *q_, *af_;
    cudaGetSymbolAddress((void**)&W1,  g_W1);
    cudaGetSymbolAddress((void**)&W2,  g_W2);
    cudaGetSymbolAddress((void**)&S1,  g_S1);
    cudaGetSymbolAddress((void**)&S2,  g_S2);
    cudaGetSymbolAddress((void**)&k_,  g_k);
    cudaGetSymbolAddress((void**)&v_,  g_v);
    cudaGetSymbolAddress((void**)&h_,  g_h);
    cudaGetSymbolAddress((void**)&a_,  g_a);
    cudaGetSymbolAddress((void**)&e_,  g_e);
    cudaGetSymbolAddress((void**)&dh_, g_dh);
    cudaGetSymbolAddress((void**)&g1_, g_g1);
    cudaGetSymbolAddress((void**)&g2_, g_g2);
    cudaGetSymbolAddress((void**)&q_,  g_q);
    cudaGetSymbolAddress((void**)&af_, g_af);

    // init memory state
    cudaMemcpyAsync(W1, mw1, sizeof(float) * D * H, cudaMemcpyDeviceToDevice);
    cudaMemcpyAsync(W2, mw2, sizeof(float) * H * D, cudaMemcpyDeviceToDevice);
    cudaMemsetAsync(S1, 0, sizeof(float) * D * H);
    cudaMemsetAsync(S2, 0, sizeof(float) * H * D);

    const float escale = 2.0f / (float)(NROWS * D);

    for (int t = 0; t < NCHUNK; ++t) {
        // k = xc @ w_k ; v = xc @ w_v  (chunk rows gathered in the A-tile load)
        gemm_kernel<false, false, EPI_NONE, true><<<gemm_grid(NROWS, D), 128>>>(
            x, w_k, k_, NROWS, D, D, nullptr, nullptr, 0.f, t);
        gemm_kernel<false, false, EPI_NONE, true><<<gemm_grid(NROWS, D), 128>>>(
            x, w_v, v_, NROWS, D, D, nullptr, nullptr, 0.f, t);
        // h = k @ W1 ; a = gelu(h)
        gemm_kernel<false, false, EPI_GELU_H, false><<<gemm_grid(NROWS, H), 128>>>(
            k_, W1, a_, NROWS, H, D, nullptr, h_, 0.f, 0);
        // e = (a @ W2 - v) * 2/(N*D)
        gemm_kernel<false, false, EPI_SUBSCALE, false><<<gemm_grid(NROWS, D), 128>>>(
            a_, W2, e_, NROWS, D, H, v_, nullptr, escale, 0);
        // g2 = a^T @ e        [H, D]
        gemm_kernel<true, false, EPI_NONE, false><<<gemm_grid(H, D), 128>>>(
            a_, e_, g2_, H, D, NROWS, nullptr, nullptr, 0.f, 0);
        // dh = (e @ W2^T) * dgelu(h)    [N, H]
        gemm_kernel<false, true, EPI_DGELU, false><<<gemm_grid(NROWS, H), 128>>>(
            e_, W2, dh_, NROWS, H, D, h_, nullptr, 0.f, 0);
        // g1 = k^T @ dh       [D, H]
        gemm_kernel<true, false, EPI_NONE, false><<<gemm_grid(D, H), 128>>>(
            k_, dh_, g1_, D, H, NROWS, nullptr, nullptr, 0.f, 0);
        // S/W updates
        update_kernel<<<(2 * D * H + 255) / 256, 256>>>(a_t, l_t, dc_t, um);
    }

    // read-out: out = gelu((x @ w_q) @ W1) @ W2
    gemm_kernel<false, false, EPI_NONE, false><<<gemm_grid(TOTROWS, D), 128>>>(
        x, w_q, q_, TOTROWS, D, D, nullptr, nullptr, 0.f, 0);
    gemm_kernel<false, false, EPI_GELU, false><<<gemm_grid(TOTROWS, H), 128>>>(
        q_, W1, af_, TOTROWS, H, D, nullptr, nullptr, 0.f, 0);
    gemm_kernel<false, false, EPI_NONE, false><<<gemm_grid(TOTROWS, D), 128>>>(
        af_, W2, out, TOTROWS, D, H, nullptr, nullptr, 0.f, 0);
}

// round 8
// speedup vs baseline: 2.6960x; 1.3702x over previous
#include <cuda_runtime.h>
#include <math.h>
#include <stdint.h>

#define D      512
#define H      1024
#define SEQ    4096
#define BATCH  4
#define CHUNK  256
#define NCHUNK 16
#define NROWS  (BATCH * CHUNK)   // 1024 rows per chunk step
#define TOTROWS (BATCH * SEQ)    // 16384 rows total

// ---------------- scratch (static device allocations; alloc-free at runtime) ----
__device__ float g_W1[D * H];
__device__ float g_W2[H * D];
__device__ float g_S1[D * H];
__device__ float g_S2[H * D];
__device__ float g_kall[TOTROWS * D];
__device__ float g_vall[TOTROWS * D];
__device__ float g_q   [TOTROWS * D];
__device__ float g_h [NROWS * H];
__device__ float g_a [NROWS * H];
__device__ float g_e [NROWS * D];
__device__ float g_dh[NROWS * H];
__device__ float g_af[TOTROWS * H];

// ---------------- math helpers --------------------------------------------------
__device__ __forceinline__ float gelu_exact(float x) {
    return 0.5f * x * (1.0f + erff(x * 0.70710678118654752f));
}
__device__ __forceinline__ float dgelu_exact(float x) {
    return 0.5f * (1.0f + erff(x * 0.70710678118654752f))
         + x * 0.39894228040143268f * expf(-0.5f * x * x);
}
__device__ __forceinline__ uint32_t f2tf(float x) {
    uint32_t u;
    asm("cvt.rna.tf32.f32 %0, %1;" : "=r"(u) : "f"(x));
    return u;
}
__device__ __forceinline__ float sigm(float x) { return 1.0f / (1.0f + expf(-x)); }
__device__ __forceinline__ int chunk_map(int row, int t) {
    return (row >> 8) * SEQ + t * CHUNK + (row & 255);
}

// ---------------- epilogue modes -------------------------------------------------
#define EPI_NONE     0   // C = AB
#define EPI_GELU_H   1   // aux2 = AB; C = gelu(AB)
#define EPI_SUBSCALE 2   // C = (AB - aux[mapped]) * scale
#define EPI_DGELU    3   // C = AB * dgelu(aux)
#define EPI_GELU     4   // C = gelu(AB)

#define ASTRIDE 36   // 36 % 32 == 4  -> A-frag LDS banks (4g + tg) unique
#define BSTRIDE 72   // 72 % 32 == 8  -> B-frag LDS banks (8tg + g) unique

__device__ __forceinline__ void mma_tf32(float c[4], const uint32_t a[4], const uint32_t b[2]) {
    asm volatile(
        "mma.sync.aligned.m16n8k8.row.col.f32.tf32.tf32.f32 "
        "{%0,%1,%2,%3}, {%4,%5,%6,%7}, {%8,%9}, {%0,%1,%2,%3};"
        : "+f"(c[0]), "+f"(c[1]), "+f"(c[2]), "+f"(c[3])
        : "r"(a[0]), "r"(a[1]), "r"(a[2]), "r"(a[3]), "r"(b[0]), "r"(b[1]));
}

// ======== pipelined 64x64x32 tf32 GEMM, 128 threads, double-buffered SMEM =======
// C[M,N] = A[M,K] @ op(B)[K,N].  TB: B physically [N,K] row-major.
// CHUNKA: A row m -> global row chunk_map(m).  CHUNKAUX: aux row mapped likewise.
// NZ: blockIdx.z selects (B,C) pair for fused multi-output GEMMs.
template <bool TB, int EPI, bool CHUNKA, bool CHUNKAUX, int NZ>
__global__ __launch_bounds__(128)
void gemm_kernel(const float* __restrict__ A, const float* __restrict__ Bp, float* __restrict__ Cp,
                 int M, int N, int K,
                 const float* __restrict__ aux, float* __restrict__ aux2,
                 float scale, int chunk_t,
                 const float* __restrict__ Bp2, float* __restrict__ Cp2,
                 const float* __restrict__ Bp3, float* __restrict__ Cp3) {
    const float* B = Bp; float* C = Cp;
    if (NZ > 1 && blockIdx.z == 1) { B = Bp2; C = Cp2; }
    if (NZ > 2 && blockIdx.z == 2) { B = Bp3; C = Cp3; }

    __shared__ __align__(16) uint32_t As[2][64 * ASTRIDE];
    __shared__ __align__(16) uint32_t Bs[2][32 * BSTRIDE];

    const int tid  = threadIdx.x;
    const int lane = tid & 31;
    const int warp = tid >> 5;
    const int g  = lane >> 2;
    const int tg = lane & 3;
    const int wm = warp >> 1;
    const int wn = warp & 1;
    const int bm = blockIdx.y * 64;
    const int bn = blockIdx.x * 64;

    // ---- per-thread load/store descriptors ----
    const float* pA[4]; int a_sm[4];
    const float* pB[4]; int b_sm[4];
#pragma unroll
    for (int i = 0; i < 4; ++i) {
        int idx = tid + i * 128;
        int row = idx >> 3;
        int c4  = (idx & 7) * 4;
        int grow = bm + row;
        if (CHUNKA) grow = chunk_map(grow, chunk_t);
        pA[i]   = A + (size_t)grow * K + c4;
        a_sm[i] = row * ASTRIDE + c4;
        if (!TB) {
            int kk = idx >> 4, n4 = (idx & 15) * 4;
            pB[i]   = B + (size_t)kk * N + bn + n4;
            b_sm[i] = kk * BSTRIDE + n4;
        } else {
            int n = idx & 63, c4b = (idx >> 6) * 4;
            pB[i]   = B + (size_t)(bn + n) * K + c4b;
            b_sm[i] = c4b * BSTRIDE + n;
        }
    }

    float4 ra[4], rb[4];
    auto ldg = [&](int k0) {
#pragma unroll
        for (int i = 0; i < 4; ++i) ra[i] = *(const float4*)(pA[i] + k0);
#pragma unroll
        for (int i = 0; i < 4; ++i)
            rb[i] = TB ? *(const float4*)(pB[i] + k0)
                       : *(const float4*)(pB[i] + (size_t)k0 * N);
    };
    auto sts = [&](int buf) {
#pragma unroll
        for (int i = 0; i < 4; ++i)
            *(uint4*)&As[buf][a_sm[i]] =
                make_uint4(f2tf(ra[i].x), f2tf(ra[i].y), f2tf(ra[i].z), f2tf(ra[i].w));
#pragma unroll
        for (int i = 0; i < 4; ++i) {
            if (!TB) {
                *(uint4*)&Bs[buf][b_sm[i]] =
                    make_uint4(f2tf(rb[i].x), f2tf(rb[i].y), f2tf(rb[i].z), f2tf(rb[i].w));
            } else {
                Bs[buf][b_sm[i] + 0 * BSTRIDE] = f2tf(rb[i].x);
                Bs[buf][b_sm[i] + 1 * BSTRIDE] = f2tf(rb[i].y);
                Bs[buf][b_sm[i] + 2 * BSTRIDE] = f2tf(rb[i].z);
                Bs[buf][b_sm[i] + 3 * BSTRIDE] = f2tf(rb[i].w);
            }
        }
    };

    float c[2][4][4] = {};
    auto mmas = [&](int buf) {
#pragma unroll
        for (int kk = 0; kk < 32; kk += 8) {
            uint32_t af[2][4], bf[4][2];
#pragma unroll
            for (int mt = 0; mt < 2; ++mt) {
                int r0 = wm * 32 + mt * 16;
                af[mt][0] = As[buf][(r0 + g)     * ASTRIDE + kk + tg];
                af[mt][1] = As[buf][(r0 + g + 8) * ASTRIDE + kk + tg];
                af[mt][2] = As[buf][(r0 + g)     * ASTRIDE + kk + tg + 4];
                af[mt][3] = As[buf][(r0 + g + 8) * ASTRIDE + kk + tg + 4];
            }
#pragma unroll
            for (int nt = 0; nt < 4; ++nt) {
                int cn = wn * 32 + nt * 8 + g;
                bf[nt][0] = Bs[buf][(kk + tg)     * BSTRIDE + cn];
                bf[nt][1] = Bs[buf][(kk + tg + 4) * BSTRIDE + cn];
            }
#pragma unroll
            for (int mt = 0; mt < 2; ++mt)
#pragma unroll
                for (int nt = 0; nt < 4; ++nt)
                    mma_tf32(c[mt][nt], af[mt], bf[nt]);
        }
    };

    const int nK = K >> 5;
    ldg(0); sts(0); __syncthreads();
    for (int t8 = 0; t8 < nK; ++t8) {
        if (t8 + 1 < nK) ldg((t8 + 1) << 5);
        mmas(t8 & 1);
        if (t8 + 1 < nK) sts((t8 + 1) & 1);
        __syncthreads();
    }

    // ---- epilogue ----
#pragma unroll
    for (int mt = 0; mt < 2; ++mt) {
#pragma unroll
        for (int nt = 0; nt < 4; ++nt) {
#pragma unroll
            for (int half = 0; half < 2; ++half) {
                int row = bm + wm * 32 + mt * 16 + g + half * 8;
                int col = bn + wn * 32 + nt * 8 + 2 * tg;
                size_t cidx = (size_t)row * N + col;
                size_t aidx = cidx;
                if (CHUNKAUX) aidx = (size_t)chunk_map(row, chunk_t) * N + col;
                float v0 = c[mt][nt][half * 2 + 0];
                float v1 = c[mt][nt][half * 2 + 1];
                if (EPI == EPI_NONE) {
                    *(float2*)(C + cidx) = make_float2(v0, v1);
                } else if (EPI == EPI_GELU_H) {
                    *(float2*)(aux2 + cidx) = make_float2(v0, v1);
                    *(float2*)(C + cidx) = make_float2(gelu_exact(v0), gelu_exact(v1));
                } else if (EPI == EPI_SUBSCALE) {
                    float2 a2 = *(const float2*)(aux + aidx);
                    *(float2*)(C + cidx) = make_float2((v0 - a2.x) * scale, (v1 - a2.y) * scale);
                } else if (EPI == EPI_DGELU) {
                    float2 a2 = *(const float2*)(aux + aidx);
                    *(float2*)(C + cidx) = make_float2(v0 * dgelu_exact(a2.x), v1 * dgelu_exact(a2.y));
                } else if (EPI == EPI_GELU) {
                    *(float2*)(C + cidx) = make_float2(gelu_exact(v0), gelu_exact(v1));
                }
            }
        }
    }
}

// ======== merged g1/g2 + fused momentum/weight update ===========================
// z=0: G2 = a^T @ e  [H,D]  -> S2,W2 update.   z=1: G1 = k^T @ dh [D,H] -> S1,W1.
// A^T layout: A physically [K=1024 rows, M cols]; z=1's A (k_all) rows are chunked.
__global__ __launch_bounds__(128)
void gradupd_kernel(const float* __restrict__ a_mat, const float* __restrict__ e_mat,
                    const float* __restrict__ k_all, const float* __restrict__ dh_mat,
                    float* __restrict__ W1p, float* __restrict__ S1p,
                    float* __restrict__ W2p, float* __restrict__ S2p,
                    const float* __restrict__ sa, const float* __restrict__ sl,
                    const float* __restrict__ sd, const int* __restrict__ um,
                    int chunk_t) {
    const int z = blockIdx.z;
    const int Mz = z ? D : H;
    const int Nz = z ? H : D;
    const float* A = z ? k_all  : a_mat;
    const float* B = z ? dh_mat : e_mat;
    float* W = z ? W1p : W2p;
    float* S = z ? S1p : S2p;
    const bool chA = (z == 1);

    const int bx = blockIdx.x;   // 0..127
    int bm, bn;
    if (z) { bn = (bx & 15) * 64; bm = (bx >> 4) * 64; }
    else   { bn = (bx & 7)  * 64; bm = (bx >> 3) * 64; }

    __shared__ __align__(16) uint32_t As[2][64 * ASTRIDE];
    __shared__ __align__(16) uint32_t Bs[2][32 * BSTRIDE];

    const int tid  = threadIdx.x;
    const int lane = tid & 31;
    const int warp = tid >> 5;
    const int g  = lane >> 2;
    const int tg = lane & 3;
    const int wm = warp >> 1;
    const int wn = warp & 1;

    const int du = *um;
    float alpha = 0.f, lr = 0.f, decay = 0.f;
    if (du) { alpha = sigm(*sa); lr = sigm(*sl); decay = sigm(*sd); }

    // A (transposed op): thread i handles k-row (k0 + kk), 4 consecutive m at m4.
    int a_kk[4]; const float* pA[4]; int a_sm[4];
    const float* pB[4]; int b_sm[4];
#pragma unroll
    for (int i = 0; i < 4; ++i) {
        int idx = tid + i * 128;
        int kk = idx & 31;
        int m4 = (idx >> 5) * 4;
        a_kk[i] = kk;
        pA[i]   = A + bm + m4;
        a_sm[i] = m4 * ASTRIDE + kk;
        int kb = idx >> 4, n4 = (idx & 15) * 4;
        pB[i]   = B + (size_t)kb * Nz + bn + n4;
        b_sm[i] = kb * BSTRIDE + n4;
    }

    float4 ra[4], rb[4];
    auto ldg = [&](int k0) {
#pragma unroll
        for (int i = 0; i < 4; ++i) {
            int row = k0 + a_kk[i];
            if (chA) row = chunk_map(row, chunk_t);
            ra[i] = *(const float4*)(pA[i] + (size_t)row * Mz);
        }
#pragma unroll
        for (int i = 0; i < 4; ++i)
            rb[i] = *(const float4*)(pB[i] + (size_t)k0 * Nz);
    };
    auto sts = [&](int buf) {
#pragma unroll
        for (int i = 0; i < 4; ++i) {
            As[buf][a_sm[i] + 0 * ASTRIDE] = f2tf(ra[i].x);
            As[buf][a_sm[i] + 1 * ASTRIDE] = f2tf(ra[i].y);
            As[buf][a_sm[i] + 2 * ASTRIDE] = f2tf(ra[i].z);
            As[buf][a_sm[i] + 3 * ASTRIDE] = f2tf(ra[i].w);
        }
#pragma unroll
        for (int i = 0; i < 4; ++i)
            *(uint4*)&Bs[buf][b_sm[i]] =
                make_uint4(f2tf(rb[i].x), f2tf(rb[i].y), f2tf(rb[i].z), f2tf(rb[i].w));
    };

    float c[2][4][4] = {};
    auto mmas = [&](int buf) {
#pragma unroll
        for (int kk = 0; kk < 32; kk += 8) {
            uint32_t af[2][4], bf[4][2];
#pragma unroll
            for (int mt = 0; mt < 2; ++mt) {
                int r0 = wm * 32 + mt * 16;
                af[mt][0] = As[buf][(r0 + g)     * ASTRIDE + kk + tg];
                af[mt][1] = As[buf][(r0 + g + 8) * ASTRIDE + kk + tg];
                af[mt][2] = As[buf][(r0 + g)     * ASTRIDE + kk + tg + 4];
                af[mt][3] = As[buf][(r0 + g + 8) * ASTRIDE + kk + tg + 4];
            }
#pragma unroll
            for (int nt = 0; nt < 4; ++nt) {
                int cn = wn * 32 + nt * 8 + g;
                bf[nt][0] = Bs[buf][(kk + tg)     * BSTRIDE + cn];
                bf[nt][1] = Bs[buf][(kk + tg + 4) * BSTRIDE + cn];
            }
#pragma unroll
            for (int mt = 0; mt < 2; ++mt)
#pragma unroll
                for (int nt = 0; nt < 4; ++nt)
                    mma_tf32(c[mt][nt], af[mt], bf[nt]);
        }
    };

    const int nK = NROWS >> 5;   // 32
    ldg(0); sts(0); __syncthreads();
    for (int t8 = 0; t8 < nK; ++t8) {
        if (t8 + 1 < nK) ldg((t8 + 1) << 5);
        mmas(t8 & 1);
        if (t8 + 1 < nK) sts((t8 + 1) & 1);
        __syncthreads();
    }

    if (!du) return;
#pragma unroll
    for (int mt = 0; mt < 2; ++mt) {
#pragma unroll
        for (int nt = 0; nt < 4; ++nt) {
#pragma unroll
            for (int half = 0; half < 2; ++half) {
                int row = bm + wm * 32 + mt * 16 + g + half * 8;
                int col = bn + wn * 32 + nt * 8 + 2 * tg;
                size_t idx = (size_t)row * Nz + col;
                float v0 = c[mt][nt][half * 2 + 0];
                float v1 = c[mt][nt][half * 2 + 1];
                float2 Sv = *(const float2*)(S + idx);
                float2 Wv = *(const float2*)(W + idx);
                float s0 = decay * Sv.x - lr * v0;
                float s1 = decay * Sv.y - lr * v1;
                *(float2*)(S + idx) = make_float2(s0, s1);
                *(float2*)(W + idx) = make_float2((1.0f - alpha) * Wv.x + s0,
                                                  (1.0f - alpha) * Wv.y + s1);
            }
        }
    }
}

// ---------------- launch ---------------------------------------------------------
extern "C" void kernel_launch(void* const* d_in, const int* in_sizes, int n_in,
                              void* d_out, int out_size) {
    const float* x    = (const float*)d_in[0];
    const float* w_q  = (const float*)d_in[1];
    const float* w_k  = (const float*)d_in[2];
    const float* w_v  = (const float*)d_in[3];
    const float* mw1  = (const float*)d_in[4];
    const float* mw2  = (const float*)d_in[5];
    const float* a_t  = (const float*)d_in[6];
    const float* l_t  = (const float*)d_in[7];
    const float* dc_t = (const float*)d_in[8];
    const int*   um   = (const int*)  d_in[9];
    float* out = (float*)d_out;

    float *W1, *W2, *S1, *S2, *kall, *vall, *q_, *h_, *a_, *e_, *dh_, *af_;
    cudaGetSymbolAddress((void**)&W1,   g_W1);
    cudaGetSymbolAddress((void**)&W2,   g_W2);
    cudaGetSymbolAddress((void**)&S1,   g_S1);
    cudaGetSymbolAddress((void**)&S2,   g_S2);
    cudaGetSymbolAddress((void**)&kall, g_kall);
    cudaGetSymbolAddress((void**)&vall, g_vall);
    cudaGetSymbolAddress((void**)&q_,   g_q);
    cudaGetSymbolAddress((void**)&h_,   g_h);
    cudaGetSymbolAddress((void**)&a_,   g_a);
    cudaGetSymbolAddress((void**)&e_,   g_e);
    cudaGetSymbolAddress((void**)&dh_,  g_dh);
    cudaGetSymbolAddress((void**)&af_,  g_af);

    cudaMemcpyAsync(W1, mw1, sizeof(float) * D * H, cudaMemcpyDeviceToDevice);
    cudaMemcpyAsync(W2, mw2, sizeof(float) * H * D, cudaMemcpyDeviceToDevice);
    cudaMemsetAsync(S1, 0, sizeof(float) * D * H);
    cudaMemsetAsync(S2, 0, sizeof(float) * H * D);

    const float escale = 2.0f / (float)(NROWS * D);

    // fused projections: k_all = x@w_k, v_all = x@w_v, q = x@w_q  (recurrence-free)
    gemm_kernel<false, EPI_NONE, false, false, 3><<<dim3(D / 64, TOTROWS / 64, 3), 128>>>(
        x, w_k, kall, TOTROWS, D, D, nullptr, nullptr, 0.f, 0, w_v, vall, w_q, q_);

    for (int t = 0; t < NCHUNK; ++t) {
        // h = k_chunk @ W1 ; a = gelu(h)
        gemm_kernel<false, EPI_GELU_H, true, false, 1><<<dim3(H / 64, NROWS / 64), 128>>>(
            kall, W1, a_, NROWS, H, D, nullptr, h_, 0.f, t, nullptr, nullptr, nullptr, nullptr);
        // e = (a @ W2 - v_chunk) * 2/(N*D)
        gemm_kernel<false, EPI_SUBSCALE, false, true, 1><<<dim3(D / 64, NROWS / 64), 128>>>(
            a_, W2, e_, NROWS, D, H, vall, nullptr, escale, t, nullptr, nullptr, nullptr, nullptr);
        // dh = (e @ W2^T) * dgelu(h)
        gemm_kernel<true, EPI_DGELU, false, false, 1><<<dim3(H / 64, NROWS / 64), 128>>>(
            e_, W2, dh_, NROWS, H, D, h_, nullptr, 0.f, 0, nullptr, nullptr, nullptr, nullptr);
        // merged g2/g1 + fused S/W updates
        gradupd_kernel<<<dim3(128, 1, 2), 128>>>(a_, e_, kall, dh_, W1, S1, W2, S2,
                                                 a_t, l_t, dc_t, um, t);
    }

    // read-out: out = gelu(q @ W1) @ W2
    gemm_kernel<false, EPI_GELU, false, false, 1><<<dim3(H / 64, TOTROWS / 64), 128>>>(
        q_, W1, af_, TOTROWS, H, D, nullptr, nullptr, 0.f, 0, nullptr, nullptr, nullptr, nullptr);
    gemm_kernel<false, EPI_NONE, false, false, 1><<<dim3(D / 64, TOTROWS / 64), 128>>>(
        af_, W2, out, TOTROWS, D, H, nullptr, nullptr, 0.f, 0, nullptr, nullptr, nullptr, nullptr);
}

// round 10
// speedup vs baseline: 2.8862x; 1.0705x over previous
#include <cuda_runtime.h>
#include <math.h>
#include <stdint.h>

#define D      512
#define H      1024
#define SEQ    4096
#define BATCH  4
#define CHUNK  256
#define NCHUNK 16
#define NROWS  (BATCH * CHUNK)   // 1024 rows per chunk step
#define TOTROWS (BATCH * SEQ)    // 16384 rows total

#define STAGES    4
#define STG_ELEMS 2304                      // 64*36 == 32*72
#define SMEM_BYTES (STAGES * 2 * STG_ELEMS * 4)   // 73728

// ---------------- scratch ---------------------------------------------------------
__device__ float g_W1[D * H];
__device__ float g_W2[H * D];
__device__ float g_S1[D * H];
__device__ float g_S2[H * D];
__device__ float g_g2[H * D];
__device__ float g_kall[TOTROWS * D];
__device__ float g_vall[TOTROWS * D];
__device__ float g_q   [TOTROWS * D];
__device__ float g_h [NROWS * H];
__device__ float g_a [NROWS * H];
__device__ float g_e [NROWS * D];
__device__ float g_dh[NROWS * H];
__device__ float g_af[TOTROWS * H];

// ---------------- helpers ---------------------------------------------------------
__device__ __forceinline__ float gelu_exact(float x) {
    return 0.5f * x * (1.0f + erff(x * 0.70710678118654752f));
}
__device__ __forceinline__ float dgelu_exact(float x) {
    return 0.5f * (1.0f + erff(x * 0.70710678118654752f))
         + x * 0.39894228040143268f * expf(-0.5f * x * x);
}
__device__ __forceinline__ uint32_t f2tf(float x) {
    uint32_t u;
    asm("cvt.rna.tf32.f32 %0, %1;" : "=r"(u) : "f"(x));
    return u;
}
__device__ __forceinline__ float sigm(float x) { return 1.0f / (1.0f + expf(-x)); }
__device__ __forceinline__ int chunk_map(int row, int t) {
    return (row >> 8) * SEQ + t * CHUNK + (row & 255);
}
__device__ __forceinline__ void cp16(uint32_t dst, const void* src) {
    asm volatile("cp.async.cg.shared.global [%0], [%1], 16;" :: "r"(dst), "l"(src));
}
__device__ __forceinline__ void cp_commit() {
    asm volatile("cp.async.commit_group;");
}
template <int N>
__device__ __forceinline__ void cp_wait() {
    asm volatile("cp.async.wait_group %0;" :: "n"(N));
}
__device__ __forceinline__ void mma_tf32(float c[4], const uint32_t a[4], const uint32_t b[2]) {
    asm volatile(
        "mma.sync.aligned.m16n8k8.row.col.f32.tf32.tf32.f32 "
        "{%0,%1,%2,%3}, {%4,%5,%6,%7}, {%8,%9}, {%0,%1,%2,%3};"
        : "+f"(c[0]), "+f"(c[1]), "+f"(c[2]), "+f"(c[3])
        : "r"(a[0]), "r"(a[1]), "r"(a[2]), "r"(a[3]), "r"(b[0]), "r"(b[1]));
}

#define EPI_NONE     0
#define EPI_GELU_H   1
#define EPI_SUBSCALE 2
#define EPI_DGELU    3
#define EPI_GELU     4
#define EPI_GRADUP   5   // fused S/W update from accumulated gradient

// ======== cp.async-pipelined 64x64x32 tf32 GEMM core ============================
// C[M,N] = op(A)[M,K] @ op(B)[K,N].
// TA: A physically [K,M] (k-rows, m-contig)  -> SMEM layout [k][m] stride 72.
// !TA: A [M,K] (k-contig)                    -> SMEM layout [m][k] stride 36.
// TB: B physically [N,K] (k-contig)          -> SMEM layout [n][k] stride 36.
// !TB: B [K,N] (n-contig)                    -> SMEM layout [k][n] stride 72.
// CHUNKA: A's k-rows (TA) or m-rows (!TA) pass through chunk_map.
// CHUNKAUX: aux row index chunk-mapped (EPI_SUBSCALE v-lookup).
template <bool TA, bool TB, int EPI, bool CHUNKA, bool CHUNKAUX>
__device__ __forceinline__ void gemm_device(
    const float* __restrict__ A, const float* __restrict__ B, float* __restrict__ C,
    int M, int N, int K,
    const float* __restrict__ aux, float* __restrict__ aux2,
    float scale, int chunk_t, int bx, int by,
    float* __restrict__ W, float* __restrict__ S,
    float alpha, float lr, float decay, int du) {

    extern __shared__ float smem[];
    float* AsBase = smem;
    float* BsBase = smem + STAGES * STG_ELEMS;

    const int tid  = threadIdx.x;
    const int lane = tid & 31;
    const int warp = tid >> 5;
    const int g  = lane >> 2;
    const int tg = lane & 3;
    const int wm = warp >> 1;
    const int wn = warp & 1;
    const int bm = by * 64;
    const int bn = bx * 64;

    // per-thread load descriptors (4 x 16B chunks per operand)
    const float* pA[4]; int a_kk[4]; int a_sm[4];
    const float* pB[4]; int b_sm[4];
#pragma unroll
    for (int i = 0; i < 4; ++i) {
        int idx = tid + i * 128;
        if (!TA) {
            int row = idx >> 3, c4 = (idx & 7) * 4;
            int grow = bm + row;
            if (CHUNKA) grow = chunk_map(grow, chunk_t);
            pA[i]   = A + (size_t)grow * K + c4;
            a_sm[i] = row * 36 + c4;
            a_kk[i] = 0;
        } else {
            int kk = idx >> 4, m4 = (idx & 15) * 4;
            a_kk[i] = kk;
            pA[i]   = A + bm + m4;
            a_sm[i] = kk * 72 + m4;
        }
        if (!TB) {
            int kb = idx >> 4, n4 = (idx & 15) * 4;
            pB[i]   = B + (size_t)kb * N + bn + n4;
            b_sm[i] = kb * 72 + n4;
        } else {
            int n = idx >> 3, c4 = (idx & 7) * 4;
            pB[i]   = B + (size_t)(bn + n) * K + c4;
            b_sm[i] = n * 36 + c4;
        }
    }

    const uint32_t as_u0 = (uint32_t)__cvta_generic_to_shared(AsBase);
    const uint32_t bs_u0 = (uint32_t)__cvta_generic_to_shared(BsBase);

    auto load_stage = [&](int t8) {
        int s = t8 & (STAGES - 1);
        uint32_t as_u = as_u0 + (uint32_t)(s * STG_ELEMS * 4);
        uint32_t bs_u = bs_u0 + (uint32_t)(s * STG_ELEMS * 4);
        int k0 = t8 << 5;
#pragma unroll
        for (int i = 0; i < 4; ++i) {
            if (!TA) {
                cp16(as_u + a_sm[i] * 4, pA[i] + k0);
            } else {
                int row = k0 + a_kk[i];
                if (CHUNKA) row = chunk_map(row, chunk_t);
                cp16(as_u + a_sm[i] * 4, pA[i] + (size_t)row * M);
            }
        }
#pragma unroll
        for (int i = 0; i < 4; ++i) {
            if (!TB) cp16(bs_u + b_sm[i] * 4, pB[i] + (size_t)k0 * N);
            else     cp16(bs_u + b_sm[i] * 4, pB[i] + k0);
        }
        cp_commit();
    };

    float c[2][4][4] = {};
    auto mmas = [&](int t8) {
        int s = t8 & (STAGES - 1);
        const float* as = AsBase + s * STG_ELEMS;
        const float* bs = BsBase + s * STG_ELEMS;
#pragma unroll
        for (int kk = 0; kk < 32; kk += 8) {
            uint32_t af[2][4], bf[4][2];
#pragma unroll
            for (int mt = 0; mt < 2; ++mt) {
                int r0 = wm * 32 + mt * 16;
                if (!TA) {
                    af[mt][0] = f2tf(as[(r0 + g)     * 36 + kk + tg]);
                    af[mt][1] = f2tf(as[(r0 + g + 8) * 36 + kk + tg]);
                    af[mt][2] = f2tf(as[(r0 + g)     * 36 + kk + tg + 4]);
                    af[mt][3] = f2tf(as[(r0 + g + 8) * 36 + kk + tg + 4]);
                } else {
                    af[mt][0] = f2tf(as[(kk + tg)     * 72 + r0 + g]);
                    af[mt][1] = f2tf(as[(kk + tg)     * 72 + r0 + g + 8]);
                    af[mt][2] = f2tf(as[(kk + tg + 4) * 72 + r0 + g]);
                    af[mt][3] = f2tf(as[(kk + tg + 4) * 72 + r0 + g + 8]);
                }
            }
#pragma unroll
            for (int nt = 0; nt < 4; ++nt) {
                int cn = wn * 32 + nt * 8 + g;
                if (!TB) {
                    bf[nt][0] = f2tf(bs[(kk + tg)     * 72 + cn]);
                    bf[nt][1] = f2tf(bs[(kk + tg + 4) * 72 + cn]);
                } else {
                    bf[nt][0] = f2tf(bs[cn * 36 + kk + tg]);
                    bf[nt][1] = f2tf(bs[cn * 36 + kk + tg + 4]);
                }
            }
#pragma unroll
            for (int mt = 0; mt < 2; ++mt)
#pragma unroll
                for (int nt = 0; nt < 4; ++nt)
                    mma_tf32(c[mt][nt], af[mt], bf[nt]);
        }
    };

    const int nK = K >> 5;
#pragma unroll
    for (int s = 0; s < STAGES - 1; ++s) load_stage(s);
    for (int t8 = 0; t8 < nK; ++t8) {
        cp_wait<STAGES - 2>();
        __syncthreads();
        if (t8 + STAGES - 1 < nK) load_stage(t8 + STAGES - 1);
        else cp_commit();                       // keep group arithmetic exact in tail
        mmas(t8);
    }

    if (EPI == EPI_GRADUP && !du) return;

#pragma unroll
    for (int mt = 0; mt < 2; ++mt) {
#pragma unroll
        for (int nt = 0; nt < 4; ++nt) {
#pragma unroll
            for (int half = 0; half < 2; ++half) {
                int row = bm + wm * 32 + mt * 16 + g + half * 8;
                int col = bn + wn * 32 + nt * 8 + 2 * tg;
                size_t cidx = (size_t)row * N + col;
                float v0 = c[mt][nt][half * 2 + 0];
                float v1 = c[mt][nt][half * 2 + 1];
                if (EPI == EPI_NONE) {
                    *(float2*)(C + cidx) = make_float2(v0, v1);
                } else if (EPI == EPI_GELU_H) {
                    *(float2*)(aux2 + cidx) = make_float2(v0, v1);
                    *(float2*)(C + cidx) = make_float2(gelu_exact(v0), gelu_exact(v1));
                } else if (EPI == EPI_SUBSCALE) {
                    size_t aidx = CHUNKAUX ? (size_t)chunk_map(row, chunk_t) * N + col : cidx;
                    float2 a2 = *(const float2*)(aux + aidx);
                    *(float2*)(C + cidx) = make_float2((v0 - a2.x) * scale, (v1 - a2.y) * scale);
                } else if (EPI == EPI_DGELU) {
                    float2 a2 = *(const float2*)(aux + cidx);
                    *(float2*)(C + cidx) = make_float2(v0 * dgelu_exact(a2.x), v1 * dgelu_exact(a2.y));
                } else if (EPI == EPI_GELU) {
                    *(float2*)(C + cidx) = make_float2(gelu_exact(v0), gelu_exact(v1));
                } else if (EPI == EPI_GRADUP) {
                    float2 Sv = *(const float2*)(S + cidx);
                    float2 Wv = *(const float2*)(W + cidx);
                    float s0 = decay * Sv.x - lr * v0;
                    float s1 = decay * Sv.y - lr * v1;
                    *(float2*)(S + cidx) = make_float2(s0, s1);
                    *(float2*)(W + cidx) = make_float2((1.0f - alpha) * Wv.x + s0,
                                                       (1.0f - alpha) * Wv.y + s1);
                }
            }
        }
    }
}

// ======== global kernels ========================================================
__global__ void __launch_bounds__(128) proj_kernel(
    const float* __restrict__ x, const float* __restrict__ wk,
    const float* __restrict__ wv, const float* __restrict__ wq,
    float* __restrict__ kall, float* __restrict__ vall, float* __restrict__ q) {
    const float* B; float* C;
    if (blockIdx.z == 0)      { B = wk; C = kall; }
    else if (blockIdx.z == 1) { B = wv; C = vall; }
    else                      { B = wq; C = q; }
    gemm_device<false, false, EPI_NONE, false, false>(
        x, B, C, TOTROWS, D, D, nullptr, nullptr, 0.f, 0, blockIdx.x, blockIdx.y,
        nullptr, nullptr, 0.f, 0.f, 0.f, 0);
}

__global__ void __launch_bounds__(128) h_kernel(
    const float* __restrict__ kall, const float* __restrict__ W1,
    float* __restrict__ a, float* __restrict__ h, int t) {
    gemm_device<false, false, EPI_GELU_H, true, false>(
        kall, W1, a, NROWS, H, D, nullptr, h, 0.f, t, blockIdx.x, blockIdx.y,
        nullptr, nullptr, 0.f, 0.f, 0.f, 0);
}

__global__ void __launch_bounds__(128) e_kernel(
    const float* __restrict__ a, const float* __restrict__ W2,
    float* __restrict__ e, const float* __restrict__ vall, float scale, int t) {
    gemm_device<false, false, EPI_SUBSCALE, false, true>(
        a, W2, e, NROWS, D, H, vall, nullptr, scale, t, blockIdx.x, blockIdx.y,
        nullptr, nullptr, 0.f, 0.f, 0.f, 0);
}

// z=0: dh = (e @ W2^T) * dgelu(h)  [1024,H]   (16x16 blocks)
// z=1: g2 = a^T @ e                [H,D]      (8x16 blocks; bx>=8 idle)
__global__ void __launch_bounds__(128) dhg2_kernel(
    const float* __restrict__ e, const float* __restrict__ W2,
    float* __restrict__ dh, const float* __restrict__ h,
    const float* __restrict__ a, float* __restrict__ g2) {
    if (blockIdx.z == 0) {
        gemm_device<false, true, EPI_DGELU, false, false>(
            e, W2, dh, NROWS, H, D, h, nullptr, 0.f, 0, blockIdx.x, blockIdx.y,
            nullptr, nullptr, 0.f, 0.f, 0.f, 0);
    } else {
        if (blockIdx.x >= 8) return;
        gemm_device<true, false, EPI_NONE, false, false>(
            a, e, g2, H, D, NROWS, nullptr, nullptr, 0.f, 0, blockIdx.x, blockIdx.y,
            nullptr, nullptr, 0.f, 0.f, 0.f, 0);
    }
}

// z=0: g1 = k^T @ dh [D,H] with fused W1/S1 update   (16x8 blocks)
// z=1: elementwise W2/S2 update from g2 buffer       (128 blocks)
__global__ void __launch_bounds__(128) g1upd_kernel(
    const float* __restrict__ kall, const float* __restrict__ dh,
    float* __restrict__ W1, float* __restrict__ S1,
    float* __restrict__ W2, float* __restrict__ S2,
    const float* __restrict__ g2,
    const float* __restrict__ sa, const float* __restrict__ sl,
    const float* __restrict__ sd, const int* __restrict__ um, int t) {
    const int du = *um;
    float alpha = 0.f, lr = 0.f, decay = 0.f;
    if (du) { alpha = sigm(*sa); lr = sigm(*sl); decay = sigm(*sd); }
    if (blockIdx.z == 0) {
        gemm_device<true, false, EPI_GRADUP, true, false>(
            kall, dh, nullptr, D, H, NROWS, nullptr, nullptr, 0.f, t,
            blockIdx.x, blockIdx.y, W1, S1, alpha, lr, decay, du);
    } else {
        if (!du) return;
        int bid = blockIdx.y * 16 + blockIdx.x;      // 0..127
        int base = bid * 1024 + threadIdx.x;         // float4 index
#pragma unroll
        for (int j = 0; j < 8; ++j) {
            int f4 = base + j * 128;
            float4 gv = ((const float4*)g2)[f4];
            float4 Sv = ((const float4*)S2)[f4];
            float4 Wv = ((const float4*)W2)[f4];
            Sv.x = decay * Sv.x - lr * gv.x;  Sv.y = decay * Sv.y - lr * gv.y;
            Sv.z = decay * Sv.z - lr * gv.z;  Sv.w = decay * Sv.w - lr * gv.w;
            Wv.x = (1.0f - alpha) * Wv.x + Sv.x;  Wv.y = (1.0f - alpha) * Wv.y + Sv.y;
            Wv.z = (1.0f - alpha) * Wv.z + Sv.z;  Wv.w = (1.0f - alpha) * Wv.w + Sv.w;
            ((float4*)S2)[f4] = Sv;
            ((float4*)W2)[f4] = Wv;
        }
    }
}

__global__ void __launch_bounds__(128) ro1_kernel(
    const float* __restrict__ q, const float* __restrict__ W1, float* __restrict__ af) {
    gemm_device<false, false, EPI_GELU, false, false>(
        q, W1, af, TOTROWS, H, D, nullptr, nullptr, 0.f, 0, blockIdx.x, blockIdx.y,
        nullptr, nullptr, 0.f, 0.f, 0.f, 0);
}
__global__ void __launch_bounds__(128) ro2_kernel(
    const float* __restrict__ af, const float* __restrict__ W2, float* __restrict__ out) {
    gemm_device<false, false, EPI_NONE, false, false>(
        af, W2, out, TOTROWS, D, H, nullptr, nullptr, 0.f, 0, blockIdx.x, blockIdx.y,
        nullptr, nullptr, 0.f, 0.f, 0.f, 0);
}

// ---------------- launch ---------------------------------------------------------
extern "C" void kernel_launch(void* const* d_in, const int* in_sizes, int n_in,
                              void* d_out, int out_size) {
    const float* x    = (const float*)d_in[0];
    const float* w_q  = (const float*)d_in[1];
    const float* w_k  = (const float*)d_in[2];
    const float* w_v  = (const float*)d_in[3];
    const float* mw1  = (const float*)d_in[4];
    const float* mw2  = (const float*)d_in[5];
    const float* a_t  = (const float*)d_in[6];
    const float* l_t  = (const float*)d_in[7];
    const float* dc_t = (const float*)d_in[8];
    const int*   um   = (const int*)  d_in[9];
    float* out = (float*)d_out;

    static bool attr_done = false;
    if (!attr_done) {
        cudaFuncSetAttribute(proj_kernel,  cudaFuncAttributeMaxDynamicSharedMemorySize, SMEM_BYTES);
        cudaFuncSetAttribute(h_kernel,     cudaFuncAttributeMaxDynamicSharedMemorySize, SMEM_BYTES);
        cudaFuncSetAttribute(e_kernel,     cudaFuncAttributeMaxDynamicSharedMemorySize, SMEM_BYTES);
        cudaFuncSetAttribute(dhg2_kernel,  cudaFuncAttributeMaxDynamicSharedMemorySize, SMEM_BYTES);
        cudaFuncSetAttribute(g1upd_kernel, cudaFuncAttributeMaxDynamicSharedMemorySize, SMEM_BYTES);
        cudaFuncSetAttribute(ro1_kernel,   cudaFuncAttributeMaxDynamicSharedMemorySize, SMEM_BYTES);
        cudaFuncSetAttribute(ro2_kernel,   cudaFuncAttributeMaxDynamicSharedMemorySize, SMEM_BYTES);
        attr_done = true;
    }

    float *W1, *W2, *S1, *S2, *g2, *kall, *vall, *q_, *h_, *a_, *e_, *dh_, *af_;
    cudaGetSymbolAddress((void**)&W1,   g_W1);
    cudaGetSymbolAddress((void**)&W2,   g_W2);
    cudaGetSymbolAddress((void**)&S1,   g_S1);
    cudaGetSymbolAddress((void**)&S2,   g_S2);
    cudaGetSymbolAddress((void**)&g2,   g_g2);
    cudaGetSymbolAddress((void**)&kall, g_kall);
    cudaGetSymbolAddress((void**)&vall, g_vall);
    cudaGetSymbolAddress((void**)&q_,   g_q);
    cudaGetSymbolAddress((void**)&h_,   g_h);
    cudaGetSymbolAddress((void**)&a_,   g_a);
    cudaGetSymbolAddress((void**)&e_,   g_e);
    cudaGetSymbolAddress((void**)&dh_,  g_dh);
    cudaGetSymbolAddress((void**)&af_,  g_af);

    cudaMemcpyAsync(W1, mw1, sizeof(float) * D * H, cudaMemcpyDeviceToDevice);
    cudaMemcpyAsync(W2, mw2, sizeof(float) * H * D, cudaMemcpyDeviceToDevice);
    cudaMemsetAsync(S1, 0, sizeof(float) * D * H);
    cudaMemsetAsync(S2, 0, sizeof(float) * H * D);

    const float escale = 2.0f / (float)(NROWS * D);

    proj_kernel<<<dim3(D / 64, TOTROWS / 64, 3), 128, SMEM_BYTES>>>(
        x, w_k, w_v, w_q, kall, vall, q_);

    for (int t = 0; t < NCHUNK; ++t) {
        h_kernel<<<dim3(H / 64, NROWS / 64), 128, SMEM_BYTES>>>(kall, W1, a_, h_, t);
        e_kernel<<<dim3(D / 64, NROWS / 64), 128, SMEM_BYTES>>>(a_, W2, e_, vall, escale, t);
        dhg2_kernel<<<dim3(H / 64, NROWS / 64, 2), 128, SMEM_BYTES>>>(e_, W2, dh_, h_, a_, g2);
        g1upd_kernel<<<dim3(H / 64, D / 64, 2), 128, SMEM_BYTES>>>(
            kall, dh_, W1, S1, W2, S2, g2, a_t, l_t, dc_t, um, t);
    }

    ro1_kernel<<<dim3(H / 64, TOTROWS / 64), 128, SMEM_BYTES>>>(q_, W1, af_);
    ro2_kernel<<<dim3(D / 64, TOTROWS / 64), 128, SMEM_BYTES>>>(af_, W2, out);
}

// round 11
// speedup vs baseline: 3.6536x; 1.2659x over previous
#include <cuda_runtime.h>
#include <math.h>
#include <stdint.h>

#define D      512
#define H      1024
#define SEQ    4096
#define BATCH  4
#define CHUNK  256
#define NCHUNK 16
#define NROWS  (BATCH * CHUNK)   // 1024 rows per chunk step
#define TOTROWS (BATCH * SEQ)    // 16384 rows total

// ---- small (chunk) GEMM core: 64x64x32, 128 thr, 4 stages ----
#define STAGES    4
#define STG_ELEMS 2304                            // 64*36 == 32*72
#define SMEM_BYTES (STAGES * 2 * STG_ELEMS * 4)   // 73728

// ---- big GEMM core: 128x128x32, 256 thr, 3 stages ----
#define BSTAGES   3
#define BIG_A_ELE (128 * 36)                      // 4608
#define BIG_B_ELE (32 * 136)                      // 4352
#define BIG_SMEM_BYTES (BSTAGES * (BIG_A_ELE + BIG_B_ELE) * 4)   // 107520

// ---------------- scratch ---------------------------------------------------------
// _tf buffers hold tf32-rounded bit patterns (as float); fp32 buffers hold exact.
__device__ float g_W1[D * H];          // fp32 master
__device__ float g_W2[H * D];
__device__ float g_W1tf[D * H];        // tf32 shadow (GEMM operand)
__device__ float g_W2tf[H * D];
__device__ float g_S1[D * H];
__device__ float g_S2[H * D];
__device__ float g_g2[H * D];
__device__ float g_xtf [TOTROWS * D];
__device__ float g_wktf[D * D];
__device__ float g_wvtf[D * D];
__device__ float g_wqtf[D * D];
__device__ float g_kall[TOTROWS * D];  // tf32 bits
__device__ float g_vall[TOTROWS * D];  // fp32 (epilogue aux)
__device__ float g_q   [TOTROWS * D];  // tf32 bits
__device__ float g_h [NROWS * H];      // fp32 (dgelu aux)
__device__ float g_a [NROWS * H];      // tf32 bits
__device__ float g_e [NROWS * D];      // tf32 bits
__device__ float g_dh[NROWS * H];      // tf32 bits
__device__ float g_af[TOTROWS * H];    // tf32 bits

// ---------------- helpers ---------------------------------------------------------
__device__ __forceinline__ float gelu_exact(float x) {
    return 0.5f * x * (1.0f + erff(x * 0.70710678118654752f));
}
__device__ __forceinline__ float dgelu_exact(float x) {
    return 0.5f * (1.0f + erff(x * 0.70710678118654752f))
         + x * 0.39894228040143268f * expf(-0.5f * x * x);
}
__device__ __forceinline__ uint32_t f2tf(float x) {
    uint32_t u;
    asm("cvt.rna.tf32.f32 %0, %1;" : "=r"(u) : "f"(x));
    return u;
}
__device__ __forceinline__ float f2tff(float x) { return __uint_as_float(f2tf(x)); }
__device__ __forceinline__ float sigm(float x) { return 1.0f / (1.0f + expf(-x)); }
__device__ __forceinline__ int chunk_map(int row, int t) {
    return (row >> 8) * SEQ + t * CHUNK + (row & 255);
}
__device__ __forceinline__ void cp16(uint32_t dst, const void* src) {
    asm volatile("cp.async.cg.shared.global [%0], [%1], 16;" :: "r"(dst), "l"(src));
}
__device__ __forceinline__ void cp_commit() {
    asm volatile("cp.async.commit_group;");
}
template <int N>
__device__ __forceinline__ void cp_wait() {
    asm volatile("cp.async.wait_group %0;" :: "n"(N));
}
__device__ __forceinline__ void mma_tf32(float c[4], const uint32_t a[4], const uint32_t b[2]) {
    asm volatile(
        "mma.sync.aligned.m16n8k8.row.col.f32.tf32.tf32.f32 "
        "{%0,%1,%2,%3}, {%4,%5,%6,%7}, {%8,%9}, {%0,%1,%2,%3};"
        : "+f"(c[0]), "+f"(c[1]), "+f"(c[2]), "+f"(c[3])
        : "r"(a[0]), "r"(a[1]), "r"(a[2]), "r"(a[3]), "r"(b[0]), "r"(b[1]));
}

#define EPI_NONE     0
#define EPI_GELU_H   1   // aux2 = fp32 preact; C = tf32(gelu)
#define EPI_SUBSCALE 2   // C = tf32((AB - aux)*scale)
#define EPI_DGELU    3   // C = tf32(AB * dgelu(aux))
#define EPI_GELU     4   // C = tf32(gelu(AB))
#define EPI_GRADUP   5   // fused S/W update + tf32 shadow

// ======== chunk GEMM core (64x64x32): operands are tf32 bits ====================
template <bool TA, bool TB, int EPI, bool CHUNKA, bool CHUNKAUX>
__device__ __forceinline__ void gemm_device(
    const float* __restrict__ A, const float* __restrict__ B, float* __restrict__ C,
    int M, int N, int K,
    const float* __restrict__ aux, float* __restrict__ aux2,
    float scale, int chunk_t, int bx, int by,
    float* __restrict__ W, float* __restrict__ S, float* __restrict__ Wtf,
    float alpha, float lr, float decay, int du) {

    extern __shared__ float smem[];
    float* AsBase = smem;
    float* BsBase = smem + STAGES * STG_ELEMS;

    const int tid  = threadIdx.x;
    const int lane = tid & 31;
    const int warp = tid >> 5;
    const int g  = lane >> 2;
    const int tg = lane & 3;
    const int wm = warp >> 1;
    const int wn = warp & 1;
    const int bm = by * 64;
    const int bn = bx * 64;

    const float* pA[4]; int a_kk[4]; int a_sm[4];
    const float* pB[4]; int b_sm[4];
#pragma unroll
    for (int i = 0; i < 4; ++i) {
        int idx = tid + i * 128;
        if (!TA) {
            int row = idx >> 3, c4 = (idx & 7) * 4;
            int grow = bm + row;
            if (CHUNKA) grow = chunk_map(grow, chunk_t);
            pA[i]   = A + (size_t)grow * K + c4;
            a_sm[i] = row * 36 + c4;
            a_kk[i] = 0;
        } else {
            int kk = idx >> 4, m4 = (idx & 15) * 4;
            a_kk[i] = kk;
            pA[i]   = A + bm + m4;
            a_sm[i] = kk * 72 + m4;
        }
        if (!TB) {
            int kb = idx >> 4, n4 = (idx & 15) * 4;
            pB[i]   = B + (size_t)kb * N + bn + n4;
            b_sm[i] = kb * 72 + n4;
        } else {
            int n = idx >> 3, c4 = (idx & 7) * 4;
            pB[i]   = B + (size_t)(bn + n) * K + c4;
            b_sm[i] = n * 36 + c4;
        }
    }

    const uint32_t as_u0 = (uint32_t)__cvta_generic_to_shared(AsBase);
    const uint32_t bs_u0 = (uint32_t)__cvta_generic_to_shared(BsBase);

    auto load_stage = [&](int t8) {
        int s = t8 & (STAGES - 1);
        uint32_t as_u = as_u0 + (uint32_t)(s * STG_ELEMS * 4);
        uint32_t bs_u = bs_u0 + (uint32_t)(s * STG_ELEMS * 4);
        int k0 = t8 << 5;
#pragma unroll
        for (int i = 0; i < 4; ++i) {
            if (!TA) {
                cp16(as_u + a_sm[i] * 4, pA[i] + k0);
            } else {
                int row = k0 + a_kk[i];
                if (CHUNKA) row = chunk_map(row, chunk_t);
                cp16(as_u + a_sm[i] * 4, pA[i] + (size_t)row * M);
            }
        }
#pragma unroll
        for (int i = 0; i < 4; ++i) {
            if (!TB) cp16(bs_u + b_sm[i] * 4, pB[i] + (size_t)k0 * N);
            else     cp16(bs_u + b_sm[i] * 4, pB[i] + k0);
        }
        cp_commit();
    };

    float c[2][4][4] = {};
    auto mmas = [&](int t8) {
        int s = t8 & (STAGES - 1);
        const uint32_t* as = (const uint32_t*)(AsBase + s * STG_ELEMS);
        const uint32_t* bs = (const uint32_t*)(BsBase + s * STG_ELEMS);
#pragma unroll
        for (int kk = 0; kk < 32; kk += 8) {
            uint32_t af[2][4], bf[4][2];
#pragma unroll
            for (int mt = 0; mt < 2; ++mt) {
                int r0 = wm * 32 + mt * 16;
                if (!TA) {
                    af[mt][0] = as[(r0 + g)     * 36 + kk + tg];
                    af[mt][1] = as[(r0 + g + 8) * 36 + kk + tg];
                    af[mt][2] = as[(r0 + g)     * 36 + kk + tg + 4];
                    af[mt][3] = as[(r0 + g + 8) * 36 + kk + tg + 4];
                } else {
                    af[mt][0] = as[(kk + tg)     * 72 + r0 + g];
                    af[mt][1] = as[(kk + tg)     * 72 + r0 + g + 8];
                    af[mt][2] = as[(kk + tg + 4) * 72 + r0 + g];
                    af[mt][3] = as[(kk + tg + 4) * 72 + r0 + g + 8];
                }
            }
#pragma unroll
            for (int nt = 0; nt < 4; ++nt) {
                int cn = wn * 32 + nt * 8 + g;
                if (!TB) {
                    bf[nt][0] = bs[(kk + tg)     * 72 + cn];
                    bf[nt][1] = bs[(kk + tg + 4) * 72 + cn];
                } else {
                    bf[nt][0] = bs[cn * 36 + kk + tg];
                    bf[nt][1] = bs[cn * 36 + kk + tg + 4];
                }
            }
#pragma unroll
            for (int mt = 0; mt < 2; ++mt)
#pragma unroll
                for (int nt = 0; nt < 4; ++nt)
                    mma_tf32(c[mt][nt], af[mt], bf[nt]);
        }
    };

    const int nK = K >> 5;
#pragma unroll
    for (int s = 0; s < STAGES - 1; ++s) load_stage(s);
    for (int t8 = 0; t8 < nK; ++t8) {
        cp_wait<STAGES - 2>();
        __syncthreads();
        if (t8 + STAGES - 1 < nK) load_stage(t8 + STAGES - 1);
        else cp_commit();
        mmas(t8);
    }

    if (EPI == EPI_GRADUP && !du) return;

#pragma unroll
    for (int mt = 0; mt < 2; ++mt) {
#pragma unroll
        for (int nt = 0; nt < 4; ++nt) {
#pragma unroll
            for (int half = 0; half < 2; ++half) {
                int row = bm + wm * 32 + mt * 16 + g + half * 8;
                int col = bn + wn * 32 + nt * 8 + 2 * tg;
                size_t cidx = (size_t)row * N + col;
                float v0 = c[mt][nt][half * 2 + 0];
                float v1 = c[mt][nt][half * 2 + 1];
                if (EPI == EPI_NONE) {
                    *(float2*)(C + cidx) = make_float2(v0, v1);
                } else if (EPI == EPI_GELU_H) {
                    *(float2*)(aux2 + cidx) = make_float2(v0, v1);
                    *(float2*)(C + cidx) = make_float2(f2tff(gelu_exact(v0)), f2tff(gelu_exact(v1)));
                } else if (EPI == EPI_SUBSCALE) {
                    size_t aidx = CHUNKAUX ? (size_t)chunk_map(row, chunk_t) * N + col : cidx;
                    float2 a2 = *(const float2*)(aux + aidx);
                    *(float2*)(C + cidx) = make_float2(f2tff((v0 - a2.x) * scale),
                                                       f2tff((v1 - a2.y) * scale));
                } else if (EPI == EPI_DGELU) {
                    float2 a2 = *(const float2*)(aux + cidx);
                    *(float2*)(C + cidx) = make_float2(f2tff(v0 * dgelu_exact(a2.x)),
                                                       f2tff(v1 * dgelu_exact(a2.y)));
                } else if (EPI == EPI_GRADUP) {
                    float2 Sv = *(const float2*)(S + cidx);
                    float2 Wv = *(const float2*)(W + cidx);
                    float s0 = decay * Sv.x - lr * v0;
                    float s1 = decay * Sv.y - lr * v1;
                    float w0 = (1.0f - alpha) * Wv.x + s0;
                    float w1 = (1.0f - alpha) * Wv.y + s1;
                    *(float2*)(S + cidx)   = make_float2(s0, s1);
                    *(float2*)(W + cidx)   = make_float2(w0, w1);
                    *(float2*)(Wtf + cidx) = make_float2(f2tff(w0), f2tff(w1));
                }
            }
        }
    }
}

// ======== big GEMM core (128x128x32, 256 thr, warp tile 32x64) ==================
// A [M,K] row-major (tf32 bits), B [K,N] row-major (tf32 bits).
// EPIB: 0 = fp32 store, 1 = tf32-bits store, 2 = tf32(gelu) store.
template <int EPIB>
__device__ __forceinline__ void gemm_big(
    const float* __restrict__ A, const float* __restrict__ B, float* __restrict__ C,
    int N, int K, int bx, int by) {

    extern __shared__ float smem[];
    float* AsBase = smem;
    float* BsBase = smem + BSTAGES * BIG_A_ELE;

    const int tid  = threadIdx.x;
    const int lane = tid & 31;
    const int warp = tid >> 5;
    const int g  = lane >> 2;
    const int tg = lane & 3;
    const int wm = warp >> 1;    // 0..3
    const int wn = warp & 1;     // 0..1
    const int bm = by * 128;
    const int bn = bx * 128;

    const float* pA[4]; int a_sm[4];
    const float* pB[4]; int b_sm[4];
#pragma unroll
    for (int i = 0; i < 4; ++i) {
        int idx = tid + i * 256;
        int row = idx >> 3, c4 = (idx & 7) * 4;
        pA[i]   = A + (size_t)(bm + row) * K + c4;
        a_sm[i] = row * 36 + c4;
        int kb = idx >> 5, n4 = (idx & 31) * 4;
        pB[i]   = B + (size_t)kb * N + bn + n4;
        b_sm[i] = kb * 136 + n4;
    }

    const uint32_t as_u0 = (uint32_t)__cvta_generic_to_shared(AsBase);
    const uint32_t bs_u0 = (uint32_t)__cvta_generic_to_shared(BsBase);

    auto load_stage = [&](int t8, int s) {
        uint32_t as_u = as_u0 + (uint32_t)(s * BIG_A_ELE * 4);
        uint32_t bs_u = bs_u0 + (uint32_t)(s * BIG_B_ELE * 4);
        int k0 = t8 << 5;
#pragma unroll
        for (int i = 0; i < 4; ++i) cp16(as_u + a_sm[i] * 4, pA[i] + k0);
#pragma unroll
        for (int i = 0; i < 4; ++i) cp16(bs_u + b_sm[i] * 4, pB[i] + (size_t)k0 * N);
        cp_commit();
    };

    float c[2][8][4] = {};
    auto mmas = [&](int s) {
        const uint32_t* as = (const uint32_t*)(AsBase + s * BIG_A_ELE);
        const uint32_t* bs = (const uint32_t*)(BsBase + s * BIG_B_ELE);
#pragma unroll
        for (int kk = 0; kk < 32; kk += 8) {
            uint32_t af[2][4], bf[8][2];
#pragma unroll
            for (int mt = 0; mt < 2; ++mt) {
                int r0 = wm * 32 + mt * 16;
                af[mt][0] = as[(r0 + g)     * 36 + kk + tg];
                af[mt][1] = as[(r0 + g + 8) * 36 + kk + tg];
                af[mt][2] = as[(r0 + g)     * 36 + kk + tg + 4];
                af[mt][3] = as[(r0 + g + 8) * 36 + kk + tg + 4];
            }
#pragma unroll
            for (int nt = 0; nt < 8; ++nt) {
                int cn = wn * 64 + nt * 8 + g;
                bf[nt][0] = bs[(kk + tg)     * 136 + cn];
                bf[nt][1] = bs[(kk + tg + 4) * 136 + cn];
            }
#pragma unroll
            for (int mt = 0; mt < 2; ++mt)
#pragma unroll
                for (int nt = 0; nt < 8; ++nt)
                    mma_tf32(c[mt][nt], af[mt], bf[nt]);
        }
    };

    const int nK = K >> 5;
    load_stage(0, 0);
    load_stage(1, 1);
    for (int t8 = 0; t8 < nK; ++t8) {
        cp_wait<BSTAGES - 2>();
        __syncthreads();
        int nxt = t8 + BSTAGES - 1;
        if (nxt < nK) load_stage(nxt, nxt % BSTAGES);
        else cp_commit();
        mmas(t8 % BSTAGES);
    }

#pragma unroll
    for (int mt = 0; mt < 2; ++mt) {
#pragma unroll
        for (int nt = 0; nt < 8; ++nt) {
#pragma unroll
            for (int half = 0; half < 2; ++half) {
                int row = bm + wm * 32 + mt * 16 + g + half * 8;
                int col = bn + wn * 64 + nt * 8 + 2 * tg;
                size_t cidx = (size_t)row * N + col;
                float v0 = c[mt][nt][half * 2 + 0];
                float v1 = c[mt][nt][half * 2 + 1];
                if (EPIB == 0)      *(float2*)(C + cidx) = make_float2(v0, v1);
                else if (EPIB == 1) *(float2*)(C + cidx) = make_float2(f2tff(v0), f2tff(v1));
                else                *(float2*)(C + cidx) = make_float2(f2tff(gelu_exact(v0)),
                                                                      f2tff(gelu_exact(v1)));
            }
        }
    }
}

// ======== global kernels ========================================================
__global__ void __launch_bounds__(256) cvt_kernel(const float4* __restrict__ src,
                                                  float4* __restrict__ dst, int n4) {
    int i = blockIdx.x * blockDim.x + threadIdx.x;
    if (i >= n4) return;
    float4 v = src[i];
    dst[i] = make_float4(f2tff(v.x), f2tff(v.y), f2tff(v.z), f2tff(v.w));
}

// z=0: kall(tf) = x@wk; z=1: vall(fp32) = x@wv; z=2: q(tf) = x@wq
__global__ void __launch_bounds__(256) proj_kernel(
    const float* __restrict__ xtf, const float* __restrict__ wktf,
    const float* __restrict__ wvtf, const float* __restrict__ wqtf,
    float* __restrict__ kall, float* __restrict__ vall, float* __restrict__ q) {
    if (blockIdx.z == 0)
        gemm_big<1>(xtf, wktf, kall, D, D, blockIdx.x, blockIdx.y);
    else if (blockIdx.z == 1)
        gemm_big<0>(xtf, wvtf, vall, D, D, blockIdx.x, blockIdx.y);
    else
        gemm_big<1>(xtf, wqtf, q, D, D, blockIdx.x, blockIdx.y);
}

__global__ void __launch_bounds__(128) h_kernel(
    const float* __restrict__ kall, const float* __restrict__ W1tf,
    float* __restrict__ a, float* __restrict__ h, int t) {
    gemm_device<false, false, EPI_GELU_H, true, false>(
        kall, W1tf, a, NROWS, H, D, nullptr, h, 0.f, t, blockIdx.x, blockIdx.y,
        nullptr, nullptr, nullptr, 0.f, 0.f, 0.f, 0);
}

__global__ void __launch_bounds__(128) e_kernel(
    const float* __restrict__ a, const float* __restrict__ W2tf,
    float* __restrict__ e, const float* __restrict__ vall, float scale, int t) {
    gemm_device<false, false, EPI_SUBSCALE, false, true>(
        a, W2tf, e, NROWS, D, H, vall, nullptr, scale, t, blockIdx.x, blockIdx.y,
        nullptr, nullptr, nullptr, 0.f, 0.f, 0.f, 0);
}

// z=0: dh = tf32((e @ W2^T) * dgelu(h));  z=1: g2 = a^T @ e (fp32)
__global__ void __launch_bounds__(128) dhg2_kernel(
    const float* __restrict__ e, const float* __restrict__ W2tf,
    float* __restrict__ dh, const float* __restrict__ h,
    const float* __restrict__ a, float* __restrict__ g2) {
    if (blockIdx.z == 0) {
        gemm_device<false, true, EPI_DGELU, false, false>(
            e, W2tf, dh, NROWS, H, D, h, nullptr, 0.f, 0, blockIdx.x, blockIdx.y,
            nullptr, nullptr, nullptr, 0.f, 0.f, 0.f, 0);
    } else {
        if (blockIdx.x >= 8) return;
        gemm_device<true, false, EPI_NONE, false, false>(
            a, e, g2, H, D, NROWS, nullptr, nullptr, 0.f, 0, blockIdx.x, blockIdx.y,
            nullptr, nullptr, nullptr, 0.f, 0.f, 0.f, 0);
    }
}

// z=0: g1 = k^T @ dh with fused W1/S1 update; z=1: elementwise W2/S2 update from g2
__global__ void __launch_bounds__(128) g1upd_kernel(
    const float* __restrict__ kall, const float* __restrict__ dh,
    float* __restrict__ W1, float* __restrict__ S1, float* __restrict__ W1tf,
    float* __restrict__ W2, float* __restrict__ S2, float* __restrict__ W2tf,
    const float* __restrict__ g2,
    const float* __restrict__ sa, const float* __restrict__ sl,
    const float* __restrict__ sd, const int* __restrict__ um, int t) {
    const int du = *um;
    float alpha = 0.f, lr = 0.f, decay = 0.f;
    if (du) { alpha = sigm(*sa); lr = sigm(*sl); decay = sigm(*sd); }
    if (blockIdx.z == 0) {
        gemm_device<true, false, EPI_GRADUP, true, false>(
            kall, dh, nullptr, D, H, NROWS, nullptr, nullptr, 0.f, t,
            blockIdx.x, blockIdx.y, W1, S1, W1tf, alpha, lr, decay, du);
    } else {
        if (!du) return;
        int bid = blockIdx.y * 16 + blockIdx.x;      // 0..127
        int base = bid * 1024 + threadIdx.x;         // float4 index
#pragma unroll
        for (int j = 0; j < 8; ++j) {
            int f4 = base + j * 128;
            float4 gv = ((const float4*)g2)[f4];
            float4 Sv = ((const float4*)S2)[f4];
            float4 Wv = ((const float4*)W2)[f4];
            Sv.x = decay * Sv.x - lr * gv.x;  Sv.y = decay * Sv.y - lr * gv.y;
            Sv.z = decay * Sv.z - lr * gv.z;  Sv.w = decay * Sv.w - lr * gv.w;
            Wv.x = (1.0f - alpha) * Wv.x + Sv.x;  Wv.y = (1.0f - alpha) * Wv.y + Sv.y;
            Wv.z = (1.0f - alpha) * Wv.z + Sv.z;  Wv.w = (1.0f - alpha) * Wv.w + Sv.w;
            ((float4*)S2)[f4] = Sv;
            ((float4*)W2)[f4] = Wv;
            ((float4*)W2tf)[f4] = make_float4(f2tff(Wv.x), f2tff(Wv.y), f2tff(Wv.z), f2tff(Wv.w));
        }
    }
}

__global__ void __launch_bounds__(256) ro1_kernel(
    const float* __restrict__ q, const float* __restrict__ W1tf, float* __restrict__ af) {
    gemm_big<2>(q, W1tf, af, H, D, blockIdx.x, blockIdx.y);
}
__global__ void __launch_bounds__(256) ro2_kernel(
    const float* __restrict__ af, const float* __restrict__ W2tf, float* __restrict__ out) {
    gemm_big<0>(af, W2tf, out, D, H, blockIdx.x, blockIdx.y);
}

// ---------------- launch ---------------------------------------------------------
extern "C" void kernel_launch(void* const* d_in, const int* in_sizes, int n_in,
                              void* d_out, int out_size) {
    const float* x    = (const float*)d_in[0];
    const float* w_q  = (const float*)d_in[1];
    const float* w_k  = (const float*)d_in[2];
    const float* w_v  = (const float*)d_in[3];
    const float* mw1  = (const float*)d_in[4];
    const float* mw2  = (const float*)d_in[5];
    const float* a_t  = (const float*)d_in[6];
    const float* l_t  = (const float*)d_in[7];
    const float* dc_t = (const float*)d_in[8];
    const int*   um   = (const int*)  d_in[9];
    float* out = (float*)d_out;

    static bool attr_done = false;
    if (!attr_done) {
        cudaFuncSetAttribute(proj_kernel,  cudaFuncAttributeMaxDynamicSharedMemorySize, BIG_SMEM_BYTES);
        cudaFuncSetAttribute(ro1_kernel,   cudaFuncAttributeMaxDynamicSharedMemorySize, BIG_SMEM_BYTES);
        cudaFuncSetAttribute(ro2_kernel,   cudaFuncAttributeMaxDynamicSharedMemorySize, BIG_SMEM_BYTES);
        cudaFuncSetAttribute(h_kernel,     cudaFuncAttributeMaxDynamicSharedMemorySize, SMEM_BYTES);
        cudaFuncSetAttribute(e_kernel,     cudaFuncAttributeMaxDynamicSharedMemorySize, SMEM_BYTES);
        cudaFuncSetAttribute(dhg2_kernel,  cudaFuncAttributeMaxDynamicSharedMemorySize, SMEM_BYTES);
        cudaFuncSetAttribute(g1upd_kernel, cudaFuncAttributeMaxDynamicSharedMemorySize, SMEM_BYTES);
        attr_done = true;
    }

    float *W1, *W2, *W1tf, *W2tf, *S1, *S2, *g2, *xtf, *wktf, *wvtf, *wqtf;
    float *kall, *vall, *q_, *h_, *a_, *e_, *dh_, *af_;
    cudaGetSymbolAddress((void**)&W1,   g_W1);
    cudaGetSymbolAddress((void**)&W2,   g_W2);
    cudaGetSymbolAddress((void**)&W1tf, g_W1tf);
    cudaGetSymbolAddress((void**)&W2tf, g_W2tf);
    cudaGetSymbolAddress((void**)&S1,   g_S1);
    cudaGetSymbolAddress((void**)&S2,   g_S2);
    cudaGetSymbolAddress((void**)&g2,   g_g2);
    cudaGetSymbolAddress((void**)&xtf,  g_xtf);
    cudaGetSymbolAddress((void**)&wktf, g_wktf);
    cudaGetSymbolAddress((void**)&wvtf, g_wvtf);
    cudaGetSymbolAddress((void**)&wqtf, g_wqtf);
    cudaGetSymbolAddress((void**)&kall, g_kall);
    cudaGetSymbolAddress((void**)&vall, g_vall);
    cudaGetSymbolAddress((void**)&q_,   g_q);
    cudaGetSymbolAddress((void**)&h_,   g_h);
    cudaGetSymbolAddress((void**)&a_,   g_a);
    cudaGetSymbolAddress((void**)&e_,   g_e);
    cudaGetSymbolAddress((void**)&dh_,  g_dh);
    cudaGetSymbolAddress((void**)&af_,  g_af);

    cudaMemcpyAsync(W1, mw1, sizeof(float) * D * H, cudaMemcpyDeviceToDevice);
    cudaMemcpyAsync(W2, mw2, sizeof(float) * H * D, cudaMemcpyDeviceToDevice);
    cudaMemsetAsync(S1, 0, sizeof(float) * D * H);
    cudaMemsetAsync(S2, 0, sizeof(float) * H * D);

    // one-time tf32 conversions of external inputs
    cvt_kernel<<<(TOTROWS * D / 4 + 255) / 256, 256>>>((const float4*)x,   (float4*)xtf,  TOTROWS * D / 4);
    cvt_kernel<<<(D * D / 4 + 255) / 256, 256>>>((const float4*)w_k, (float4*)wktf, D * D / 4);
    cvt_kernel<<<(D * D / 4 + 255) / 256, 256>>>((const float4*)w_v, (float4*)wvtf, D * D / 4);
    cvt_kernel<<<(D * D / 4 + 255) / 256, 256>>>((const float4*)w_q, (float4*)wqtf, D * D / 4);
    cvt_kernel<<<(D * H / 4 + 255) / 256, 256>>>((const float4*)mw1, (float4*)W1tf, D * H / 4);
    cvt_kernel<<<(H * D / 4 + 255) / 256, 256>>>((const float4*)mw2, (float4*)W2tf, H * D / 4);

    const float escale = 2.0f / (float)(NROWS * D);

    proj_kernel<<<dim3(D / 128, TOTROWS / 128, 3), 256, BIG_SMEM_BYTES>>>(
        xtf, wktf, wvtf, wqtf, kall, vall, q_);

    for (int t = 0; t < NCHUNK; ++t) {
        h_kernel<<<dim3(H / 64, NROWS / 64), 128, SMEM_BYTES>>>(kall, W1tf, a_, h_, t);
        e_kernel<<<dim3(D / 64, NROWS / 64), 128, SMEM_BYTES>>>(a_, W2tf, e_, vall, escale, t);
        dhg2_kernel<<<dim3(H / 64, NROWS / 64, 2), 128, SMEM_BYTES>>>(e_, W2tf, dh_, h_, a_, g2);
        g1upd_kernel<<<dim3(H / 64, D / 64, 2), 128, SMEM_BYTES>>>(
            kall, dh_, W1, S1, W1tf, W2, S2, W2tf, g2, a_t, l_t, dc_t, um, t);
    }

    ro1_kernel<<<dim3(H / 128, TOTROWS / 128), 256, BIG_SMEM_BYTES>>>(q_, W1tf, af_);
    ro2_kernel<<<dim3(D / 128, TOTROWS / 128), 256, BIG_SMEM_BYTES>>>(af_, W2tf, out);
}